// round 8
// baseline (speedup 1.0000x reference)
#include <cuda_runtime.h>
#include <cuda_bf16.h>
#include <cstdint>

#define B    64
#define HID  768
#define VSZ  30000
#define TLEN 32
#define C1   512

// logits HMMA tiling
#define MT      128
#define KC      64
#define NCHUNK  (HID / KC)              // 12
#define GRID_L  ((VSZ + MT - 1) / MT)   // 235
#define LSTAGE  49152                   // Whi 16K | Wlo 16K | Hhi 8K | Hlo 8K

// gates HMMA tiling
#define KSG     4                       // split-K
#define CHG     6                       // chunks of 64 per split (384 k)

__device__ float g_c[B * HID];          // transposed: [u][b]
__device__ float g_hidden[B * C1];
__device__ unsigned long long g_amax[2][B];
__device__ float g_gpartT[KSG][4 * HID][B];
// merged hi/lo planes: [0 .. VSZ*HID) = hi, [VSZ*HID .. 2*VSZ*HID) = lo
__device__ __nv_bfloat16 g_W2[(size_t)2 * VSZ * HID];
__device__ __nv_bfloat16 g_Ehi[(size_t)VSZ * HID];
__device__ __nv_bfloat16 g_Elo[(size_t)VSZ * HID];
__device__ __nv_bfloat16 g_WihHi[4 * HID * HID];
__device__ __nv_bfloat16 g_WihLo[4 * HID * HID];
__device__ __nv_bfloat16 g_WhhHi[4 * HID * HID];
__device__ __nv_bfloat16 g_WhhLo[4 * HID * HID];
__device__ __nv_bfloat16 g_H2[2 * B * HID];   // hi plane | lo plane

__device__ __forceinline__ unsigned int ford(float f) {
    unsigned int u = __float_as_uint(f);
    return u ^ (((int)u >> 31) | 0x80000000u);
}
__device__ __forceinline__ float sigm(float x) { return 1.0f / (1.0f + expf(-x)); }

__device__ __forceinline__ uint32_t smem_u32(const void* p) {
    uint32_t a;
    asm("{ .reg .u64 t; cvta.to.shared.u64 t, %1; cvt.u32.u64 %0, t; }" : "=r"(a) : "l"(p));
    return a;
}

#define LDSM4(r0, r1, r2, r3, addr) \
    asm volatile("ldmatrix.sync.aligned.m8n8.x4.shared.b16 {%0,%1,%2,%3}, [%4];" \
                 : "=r"(r0), "=r"(r1), "=r"(r2), "=r"(r3) : "r"(addr))

#define MMA16816(d, a, bf) \
    asm volatile("mma.sync.aligned.m16n8k16.row.col.f32.bf16.bf16.f32 " \
                 "{%0,%1,%2,%3}, {%4,%5,%6,%7}, {%8,%9}, {%0,%1,%2,%3};" \
                 : "+f"((d)[0]), "+f"((d)[1]), "+f"((d)[2]), "+f"((d)[3]) \
                 : "r"((a)[0]), "r"((a)[1]), "r"((a)[2]), "r"((a)[3]), \
                   "r"((bf)[0]), "r"((bf)[1]))

#define CPASYNC(dst, src) \
    asm volatile("cp.async.ca.shared.global [%0], [%1], 16;" :: "r"(dst), "l"(src) : "memory")
#define CPCOMMIT() asm volatile("cp.async.commit_group;" ::: "memory")
#define CPWAIT1()  asm volatile("cp.async.wait_group 1;" ::: "memory")
#define CPWAIT0()  asm volatile("cp.async.wait_group 0;" ::: "memory")

// ---------------------------------------------------------------------------
__global__ void init_kernel(const float* __restrict__ fused) {
    int i = blockIdx.x * blockDim.x + threadIdx.x;
    if (i < B * HID) {
        float v = fused[i];
        __nv_bfloat16 hi = __float2bfloat16(v);
        g_H2[i] = hi;
        g_H2[B * HID + i] = __float2bfloat16(v - __bfloat162float(hi));
        g_c[i] = 0.0f;
    }
    if (blockIdx.x == 0 && threadIdx.x < B) {
        g_amax[0][threadIdx.x] = 0ull;
        g_amax[1][threadIdx.x] = 0ull;
    }
}

// ---------------------------------------------------------------------------
__global__ void split_kernel(const float* __restrict__ src,
                             __nv_bfloat16* __restrict__ hi,
                             __nv_bfloat16* __restrict__ lo, size_t n) {
    size_t stride = (size_t)gridDim.x * blockDim.x * 4;
    for (size_t i = ((size_t)blockIdx.x * blockDim.x + threadIdx.x) * 4; i < n; i += stride) {
        float4 x = *(const float4*)(src + i);
        __nv_bfloat16 h0 = __float2bfloat16(x.x);
        __nv_bfloat16 h1 = __float2bfloat16(x.y);
        __nv_bfloat16 h2 = __float2bfloat16(x.z);
        __nv_bfloat16 h3 = __float2bfloat16(x.w);
        hi[i] = h0; hi[i + 1] = h1; hi[i + 2] = h2; hi[i + 3] = h3;
        lo[i]     = __float2bfloat16(x.x - __bfloat162float(h0));
        lo[i + 1] = __float2bfloat16(x.y - __bfloat162float(h1));
        lo[i + 2] = __float2bfloat16(x.z - __bfloat162float(h2));
        lo[i + 3] = __float2bfloat16(x.w - __bfloat162float(h3));
    }
}

// ---------------------------------------------------------------------------
__global__ void closed1_kernel(const float* __restrict__ fused,
                               const float* __restrict__ c1_W,
                               const float* __restrict__ c1_b) {
    __shared__ float w[HID];
    int j = blockIdx.x;
    for (int k = threadIdx.x; k < HID; k += 64) w[k] = c1_W[j * HID + k];
    __syncthreads();
    int b = threadIdx.x;
    float acc = 0.0f;
    for (int k = 0; k < HID; ++k) acc += fused[b * HID + k] * w[k];
    acc += c1_b[j];
    g_hidden[b * C1 + j] = fmaxf(acc, 0.0f);
}

__global__ void closed2_kernel(const float* __restrict__ c2_W,
                               const float* __restrict__ c2_b,
                               float* __restrict__ out) {
    int wid = threadIdx.x >> 5, lane = threadIdx.x & 31;
    int o = blockIdx.x * 4 + wid;
    int b = o >> 1, cls = o & 1;
    float acc = 0.0f;
    for (int k = lane; k < C1; k += 32)
        acc += g_hidden[b * C1 + k] * c2_W[cls * C1 + k];
#pragma unroll
    for (int off = 16; off; off >>= 1)
        acc += __shfl_xor_sync(0xFFFFFFFFu, acc, off);
    if (lane == 0) out[b * 2 + cls] = acc + c2_b[cls];
}

// ---------------------------------------------------------------------------
// gates via HMMA split-bf16 (unchanged structure from round 7)
// ---------------------------------------------------------------------------
__global__ void __launch_bounds__(256, 2)
gates_mma(int t, float* __restrict__ out) {
    __shared__ __align__(128) __nv_bfloat16 sAhi[64 * KC];
    __shared__ __align__(128) __nv_bfloat16 sAlo[64 * KC];
    __shared__ __align__(128) __nv_bfloat16 sBhi[B * KC];
    __shared__ __align__(128) __nv_bfloat16 sBlo[B * KC];
    __shared__ int tok_s[B];

    const int tid = threadIdx.x, wid = tid >> 5, lane = tid & 31;
    const int mw = wid >> 1, nw = wid & 1;
    const int mtile = blockIdx.x;
    const int ks = blockIdx.y;
    const bool is_x = ks < 2;
    const int kbase = (ks & 1) * 384;

    if (tid < B) {
        int tok = 0;
        if (t > 0) tok = (int)(~(unsigned int)(g_amax[(t - 1) & 1][tid]));
        tok_s[tid] = tok;
        if (mtile == 0 && ks == 0) {
            g_amax[t & 1][tid] = 0ull;
            if (t > 0) out[2 * B + tid * TLEN + (t - 1)] = (float)tok;
        }
    }
    __syncthreads();

    const __nv_bfloat16* hhi = g_H2;
    const __nv_bfloat16* hlo = g_H2 + B * HID;

    const __nv_bfloat16* srcp[8];
    uint32_t dsta[8];
#pragma unroll
    for (int i = 0; i < 8; ++i) {
        int s = tid + i * 256;
        int r = (s & 511) >> 3, g = s & 7;
        uint32_t dst = (uint32_t)(r * 128 + ((g ^ (r & 7)) * 16));
        if (s < 512) {
            int m = mtile * 64 + r;
            srcp[i] = (is_x ? g_WihHi : g_WhhHi) + (size_t)m * HID + kbase + g * 8;
            dsta[i] = smem_u32(sAhi) + dst;
        } else if (s < 1024) {
            int m = mtile * 64 + r;
            srcp[i] = (is_x ? g_WihLo : g_WhhLo) + (size_t)m * HID + kbase + g * 8;
            dsta[i] = smem_u32(sAlo) + dst;
        } else if (s < 1536) {
            srcp[i] = is_x ? (g_Ehi + (size_t)tok_s[r] * HID + kbase + g * 8)
                           : (hhi + r * HID + kbase + g * 8);
            dsta[i] = smem_u32(sBhi) + dst;
        } else {
            srcp[i] = is_x ? (g_Elo + (size_t)tok_s[r] * HID + kbase + g * 8)
                           : (hlo + r * HID + kbase + g * 8);
            dsta[i] = smem_u32(sBlo) + dst;
        }
    }

    const int mA = mw * 16 + ((lane >> 3) & 1) * 8 + (lane & 7);
    const int gAo = lane >> 4;
    const int nB = nw * 32 + ((lane >> 4) & 1) * 8 + (lane & 7);
    const int gBo = (lane >> 3) & 1;
    const uint32_t sAhiB = smem_u32(sAhi), sAloB = smem_u32(sAlo);
    const uint32_t sBhiB = smem_u32(sBhi), sBloB = smem_u32(sBlo);

    float acc[4][4];
#pragma unroll
    for (int n = 0; n < 4; ++n)
#pragma unroll
        for (int j = 0; j < 4; ++j) acc[n][j] = 0.0f;

    uint4 pf[8];
#pragma unroll
    for (int i = 0; i < 8; ++i) { pf[i] = *(const uint4*)srcp[i]; srcp[i] += KC; }

    for (int c = 0; c < CHG; ++c) {
#pragma unroll
        for (int i = 0; i < 8; ++i)
            asm volatile("st.shared.v4.b32 [%0], {%1, %2, %3, %4};"
                         :: "r"(dsta[i]), "r"(pf[i].x), "r"(pf[i].y),
                            "r"(pf[i].z), "r"(pf[i].w) : "memory");
        __syncthreads();

        if (c + 1 < CHG) {
#pragma unroll
            for (int i = 0; i < 8; ++i) { pf[i] = *(const uint4*)srcp[i]; srcp[i] += KC; }
        }

#pragma unroll
        for (int step = 0; step < 4; ++step) {
            const int g0 = step * 2;
            const int gA = g0 + gAo;
            const uint32_t offA = (uint32_t)(mA * 128 + ((gA ^ (mA & 7)) * 16));
            uint32_t ahi[4], alo[4];
            LDSM4(ahi[0], ahi[1], ahi[2], ahi[3], sAhiB + offA);
            LDSM4(alo[0], alo[1], alo[2], alo[3], sAloB + offA);

            uint32_t bhi[4][2], blo[4][2];
#pragma unroll
            for (int ntp = 0; ntp < 2; ++ntp) {
                const int nr = nB + ntp * 16;
                const int gB = g0 + gBo;
                const uint32_t offB = (uint32_t)(nr * 128 + ((gB ^ (nr & 7)) * 16));
                LDSM4(bhi[ntp * 2][0], bhi[ntp * 2][1],
                      bhi[ntp * 2 + 1][0], bhi[ntp * 2 + 1][1], sBhiB + offB);
                LDSM4(blo[ntp * 2][0], blo[ntp * 2][1],
                      blo[ntp * 2 + 1][0], blo[ntp * 2 + 1][1], sBloB + offB);
            }
#pragma unroll
            for (int n = 0; n < 4; ++n) {
                MMA16816(acc[n], ahi, bhi[n]);
                MMA16816(acc[n], ahi, blo[n]);
                MMA16816(acc[n], alo, bhi[n]);
            }
        }
        __syncthreads();
    }

    const int laneg = lane >> 2, lane4 = lane & 3;
    const int row_lo = mtile * 64 + mw * 16 + laneg;
    const int row_hi = row_lo + 8;
#pragma unroll
    for (int n = 0; n < 4; ++n) {
        int col = nw * 32 + n * 8 + lane4 * 2;
        *(float2*)&g_gpartT[ks][row_lo][col] = make_float2(acc[n][0], acc[n][1]);
        *(float2*)&g_gpartT[ks][row_hi][col] = make_float2(acc[n][2], acc[n][3]);
    }
}

// ---------------------------------------------------------------------------
__global__ void cell_kernel(const float* __restrict__ b_ih,
                            const float* __restrict__ b_hh, int t) {
    int idx = blockIdx.x * blockDim.x + threadIdx.x;
    if (idx >= B * HID) return;
    int b = idx & (B - 1), u = idx >> 6;

    float gi = b_ih[u] + b_hh[u];
    float gf = b_ih[HID + u] + b_hh[HID + u];
    float gg = b_ih[2 * HID + u] + b_hh[2 * HID + u];
    float go = b_ih[3 * HID + u] + b_hh[3 * HID + u];
#pragma unroll
    for (int s = 0; s < KSG; ++s) {
        gi += g_gpartT[s][u][b];
        gf += g_gpartT[s][HID + u][b];
        gg += g_gpartT[s][2 * HID + u][b];
        go += g_gpartT[s][3 * HID + u][b];
    }
    float cn = sigm(gf) * g_c[u * B + b] + sigm(gi) * tanhf(gg);
    g_c[u * B + b] = cn;
    float hn = sigm(go) * tanhf(cn);
    __nv_bfloat16 hi = __float2bfloat16(hn);
    g_H2[b * HID + u] = hi;
    g_H2[B * HID + b * HID + u] = __float2bfloat16(hn - __bfloat162float(hi));
}

// ---------------------------------------------------------------------------
// logits via HMMA split-bf16, MT=128, cp.async double buffer, lean registers.
// ---------------------------------------------------------------------------
__global__ void __launch_bounds__(256, 2)
logits_mma(const float* __restrict__ out_b, int t) {
    extern __shared__ __align__(128) char dsm[];
    __shared__ unsigned long long skeys[4][B];

    const int tid = threadIdx.x, wid = tid >> 5, lane = tid & 31;
    const int mw = wid & 3, nw = wid >> 2;
    const int v0 = blockIdx.x * MT;
    const uint32_t sb0 = smem_u32(dsm);

    const char* baseW = (const char*)g_W2;
    const char* baseH = (const char*)g_H2;
    const uint32_t WLO = (uint32_t)((size_t)VSZ * HID * 2);
    const uint32_t HLO = (uint32_t)(B * HID * 2);

    // loader state: 4 W row offsets + 2 H row offsets (u32 bytes) + smem rel dst
    uint32_t woff[4], dstW[4], hoff[2], dstH[2];
#pragma unroll
    for (int i = 0; i < 4; ++i) {
        int s = tid + i * 256;           // 0..1023
        int r = s >> 3, g = s & 7;
        int v = v0 + r; if (v >= VSZ) v = VSZ - 1;
        woff[i] = (uint32_t)(((size_t)v * HID + g * 8) * 2);
        dstW[i] = (uint32_t)(r * 128 + ((g ^ (r & 7)) * 16));
    }
#pragma unroll
    for (int i = 0; i < 2; ++i) {
        int s = tid + i * 256;           // 0..511
        int r = s >> 3, g = s & 7;
        hoff[i] = (uint32_t)((r * HID + g * 8) * 2);
        dstH[i] = (uint32_t)(32768 + r * 128 + ((g ^ (r & 7)) * 16));
    }

    const int mArb = mw * 32 + ((lane >> 3) & 1) * 8 + (lane & 7);
    const int gAo = lane >> 4;
    const int nB = nw * 32 + ((lane >> 4) & 1) * 8 + (lane & 7);
    const int gBo = (lane >> 3) & 1;

    float acc[2][4][4];
#pragma unroll
    for (int mi = 0; mi < 2; ++mi)
#pragma unroll
        for (int n = 0; n < 4; ++n)
#pragma unroll
            for (int j = 0; j < 4; ++j) acc[mi][n][j] = 0.0f;

    // issue stage 0
#pragma unroll
    for (int i = 0; i < 4; ++i) {
        CPASYNC(sb0 + dstW[i], baseW + woff[i]);
        CPASYNC(sb0 + dstW[i] + 16384, baseW + woff[i] + WLO);
    }
#pragma unroll
    for (int i = 0; i < 2; ++i) {
        CPASYNC(sb0 + dstH[i], baseH + hoff[i]);
        CPASYNC(sb0 + dstH[i] + 8192, baseH + hoff[i] + HLO);
    }
    CPCOMMIT();
#pragma unroll
    for (int i = 0; i < 4; ++i) woff[i] += KC * 2;
#pragma unroll
    for (int i = 0; i < 2; ++i) hoff[i] += KC * 2;

    for (int c = 0; c < NCHUNK; ++c) {
        const uint32_t sb = sb0 + (uint32_t)(c & 1) * LSTAGE;
        if (c + 1 < NCHUNK) {
            const uint32_t nb = sb0 + (uint32_t)((c + 1) & 1) * LSTAGE;
#pragma unroll
            for (int i = 0; i < 4; ++i) {
                CPASYNC(nb + dstW[i], baseW + woff[i]);
                CPASYNC(nb + dstW[i] + 16384, baseW + woff[i] + WLO);
            }
#pragma unroll
            for (int i = 0; i < 2; ++i) {
                CPASYNC(nb + dstH[i], baseH + hoff[i]);
                CPASYNC(nb + dstH[i] + 8192, baseH + hoff[i] + HLO);
            }
            CPCOMMIT();
#pragma unroll
            for (int i = 0; i < 4; ++i) woff[i] += KC * 2;
#pragma unroll
            for (int i = 0; i < 2; ++i) hoff[i] += KC * 2;
            CPWAIT1();
        } else {
            CPWAIT0();
        }
        __syncthreads();

        const uint32_t sWhiB = sb, sWloB = sb + 16384;
        const uint32_t sHhiB = sb + 32768, sHloB = sb + 40960;
#pragma unroll
        for (int step = 0; step < 4; ++step) {
            const int g0 = step * 2;
            const int gA = g0 + gAo, gB = g0 + gBo;
            // B fragments first (live across mi loop)
            uint32_t bhi[4][2], blo[4][2];
#pragma unroll
            for (int ntp = 0; ntp < 2; ++ntp) {
                const int nr = nB + ntp * 16;
                const uint32_t offB = (uint32_t)(nr * 128 + ((gB ^ (nr & 7)) * 16));
                LDSM4(bhi[ntp * 2][0], bhi[ntp * 2][1],
                      bhi[ntp * 2 + 1][0], bhi[ntp * 2 + 1][1], sHhiB + offB);
                LDSM4(blo[ntp * 2][0], blo[ntp * 2][1],
                      blo[ntp * 2 + 1][0], blo[ntp * 2 + 1][1], sHloB + offB);
            }
            // A halves sequentially (small live window)
#pragma unroll
            for (int mi = 0; mi < 2; ++mi) {
                const int row = mArb + mi * 16;
                const uint32_t offA = (uint32_t)(row * 128 + ((gA ^ (row & 7)) * 16));
                uint32_t ahi[4], alo[4];
                LDSM4(ahi[0], ahi[1], ahi[2], ahi[3], sWhiB + offA);
                LDSM4(alo[0], alo[1], alo[2], alo[3], sWloB + offA);
#pragma unroll
                for (int n = 0; n < 4; ++n) {
                    MMA16816(acc[mi][n], ahi, bhi[n]);
                    MMA16816(acc[mi][n], ahi, blo[n]);
                    MMA16816(acc[mi][n], alo, bhi[n]);
                }
            }
        }
        __syncthreads();
    }

    // epilogue: bias + deterministic argmax
    const int laneg = lane >> 2, lane4 = lane & 3;
#pragma unroll
    for (int n = 0; n < 4; ++n) {
        unsigned long long kA = 0ull, kB = 0ull;
#pragma unroll
        for (int mi = 0; mi < 2; ++mi) {
            int ml = v0 + mw * 32 + mi * 16 + laneg, mh = ml + 8;
            if (ml < VSZ) {
                float bl = out_b[ml];
                unsigned int ni = ~(unsigned int)ml;
                unsigned long long k0 = ((unsigned long long)ford(acc[mi][n][0] + bl) << 32) | ni;
                unsigned long long k1 = ((unsigned long long)ford(acc[mi][n][1] + bl) << 32) | ni;
                if (k0 > kA) kA = k0;
                if (k1 > kB) kB = k1;
            }
            if (mh < VSZ) {
                float bh = out_b[mh];
                unsigned int ni = ~(unsigned int)mh;
                unsigned long long k2 = ((unsigned long long)ford(acc[mi][n][2] + bh) << 32) | ni;
                unsigned long long k3 = ((unsigned long long)ford(acc[mi][n][3] + bh) << 32) | ni;
                if (k2 > kA) kA = k2;
                if (k3 > kB) kB = k3;
            }
        }
#pragma unroll
        for (int off = 4; off < 32; off <<= 1) {
            unsigned long long oA = __shfl_xor_sync(0xFFFFFFFFu, kA, off);
            unsigned long long oB = __shfl_xor_sync(0xFFFFFFFFu, kB, off);
            if (oA > kA) kA = oA;
            if (oB > kB) kB = oB;
        }
        if (laneg == 0) {
            int ncol = nw * 32 + n * 8 + lane4 * 2;
            skeys[mw][ncol]     = kA;
            skeys[mw][ncol + 1] = kB;
        }
    }
    __syncthreads();
    if (tid < B) {
        unsigned long long k = skeys[0][tid];
        if (skeys[1][tid] > k) k = skeys[1][tid];
        if (skeys[2][tid] > k) k = skeys[2][tid];
        if (skeys[3][tid] > k) k = skeys[3][tid];
        atomicMax(&g_amax[t & 1][tid], k);
    }
}

// ---------------------------------------------------------------------------
__global__ void final_kernel(float* __restrict__ out) {
    int b = threadIdx.x;
    if (b < B) {
        int tok = (int)(~(unsigned int)(g_amax[(TLEN - 1) & 1][b]));
        out[2 * B + b * TLEN + (TLEN - 1)] = (float)tok;
    }
}

// ---------------------------------------------------------------------------
extern "C" void kernel_launch(void* const* d_in, const int* in_sizes, int n_in,
                              void* d_out, int out_size) {
    const float* fused = (const float*)d_in[0];
    const float* emb   = (const float*)d_in[1];
    const float* W_ih  = (const float*)d_in[2];
    const float* W_hh  = (const float*)d_in[3];
    const float* b_ih  = (const float*)d_in[4];
    const float* b_hh  = (const float*)d_in[5];
    const float* out_W = (const float*)d_in[6];
    const float* out_b = (const float*)d_in[7];
    const float* c1_W  = (const float*)d_in[8];
    const float* c1_b  = (const float*)d_in[9];
    const float* c2_W  = (const float*)d_in[10];
    const float* c2_b  = (const float*)d_in[11];
    float* out = (float*)d_out;

    cudaFuncSetAttribute(logits_mma, cudaFuncAttributeMaxDynamicSharedMemorySize,
                         2 * LSTAGE);

    __nv_bfloat16 *pW2, *pEhi, *pElo, *pIhHi, *pIhLo, *pHhHi, *pHhLo;
    cudaGetSymbolAddress((void**)&pW2, g_W2);
    cudaGetSymbolAddress((void**)&pEhi, g_Ehi);
    cudaGetSymbolAddress((void**)&pElo, g_Elo);
    cudaGetSymbolAddress((void**)&pIhHi, g_WihHi);
    cudaGetSymbolAddress((void**)&pIhLo, g_WihLo);
    cudaGetSymbolAddress((void**)&pHhHi, g_WhhHi);
    cudaGetSymbolAddress((void**)&pHhLo, g_WhhLo);

    init_kernel<<<(B * HID + 255) / 256, 256>>>(fused);
    split_kernel<<<2048, 256>>>(out_W, pW2, pW2 + (size_t)VSZ * HID, (size_t)VSZ * HID);
    split_kernel<<<2048, 256>>>(emb, pEhi, pElo, (size_t)VSZ * HID);
    split_kernel<<<512, 256>>>(W_ih, pIhHi, pIhLo, (size_t)4 * HID * HID);
    split_kernel<<<512, 256>>>(W_hh, pHhHi, pHhLo, (size_t)4 * HID * HID);
    closed1_kernel<<<C1, 64>>>(fused, c1_W, c1_b);
    closed2_kernel<<<32, 128>>>(c2_W, c2_b, out);

    dim3 ggrid(4 * HID / 64, KSG);   // (48, 4)
    for (int t = 0; t < TLEN; ++t) {
        gates_mma<<<ggrid, 256>>>(t, out);
        cell_kernel<<<(B * HID + 255) / 256, 256>>>(b_ih, b_hh, t);
        logits_mma<<<GRID_L, 256, 2 * LSTAGE>>>(out_b, t);
    }
    final_kernel<<<1, 64>>>(out);
}

// round 9
// speedup vs baseline: 1.2777x; 1.2777x over previous
#include <cuda_runtime.h>
#include <cuda_bf16.h>
#include <cstdint>

#define B    64
#define HID  768
#define VSZ  30000
#define TLEN 32
#define C1   512

// logits HMMA tiling (round-7 proven)
#define MT      128
#define KC      64
#define NCHUNK  (HID / KC)              // 12
#define GRID_L  ((VSZ + MT - 1) / MT)   // 235
#define LSTAGE  49152                   // Whi 16K | Wlo 16K | Hhi 8K | Hlo 8K

// gates: fused G = [W_ih | W_hh], unit-interleaved rows
#define GK      (2 * HID)               // 1536
#define GCH     (GK / KC)               // 24 chunks

__device__ float g_c[B * HID];          // transposed: [u][b]
__device__ float g_hidden[B * C1];
__device__ float g_bsum[4 * HID];
__device__ unsigned long long g_amax[2][B];
__device__ __nv_bfloat16 g_Whi[(size_t)VSZ * HID];
__device__ __nv_bfloat16 g_Wlo[(size_t)VSZ * HID];
__device__ __nv_bfloat16 g_Ehi[(size_t)VSZ * HID];
__device__ __nv_bfloat16 g_Elo[(size_t)VSZ * HID];
__device__ __nv_bfloat16 g_Ghi[4 * HID * GK];
__device__ __nv_bfloat16 g_Glo[4 * HID * GK];
__device__ __nv_bfloat16 g_hhi[B * HID];
__device__ __nv_bfloat16 g_hlo[B * HID];

__device__ __forceinline__ unsigned int ford(float f) {
    unsigned int u = __float_as_uint(f);
    return u ^ (((int)u >> 31) | 0x80000000u);
}
__device__ __forceinline__ float sigm(float x) { return 1.0f / (1.0f + expf(-x)); }

__device__ __forceinline__ uint32_t smem_u32(const void* p) {
    uint32_t a;
    asm("{ .reg .u64 t; cvta.to.shared.u64 t, %1; cvt.u32.u64 %0, t; }" : "=r"(a) : "l"(p));
    return a;
}

#define LDSM4(r0, r1, r2, r3, addr) \
    asm volatile("ldmatrix.sync.aligned.m8n8.x4.shared.b16 {%0,%1,%2,%3}, [%4];" \
                 : "=r"(r0), "=r"(r1), "=r"(r2), "=r"(r3) : "r"(addr))

#define MMA16816(d, a, bf) \
    asm volatile("mma.sync.aligned.m16n8k16.row.col.f32.bf16.bf16.f32 " \
                 "{%0,%1,%2,%3}, {%4,%5,%6,%7}, {%8,%9}, {%0,%1,%2,%3};" \
                 : "+f"((d)[0]), "+f"((d)[1]), "+f"((d)[2]), "+f"((d)[3]) \
                 : "r"((a)[0]), "r"((a)[1]), "r"((a)[2]), "r"((a)[3]), \
                   "r"((bf)[0]), "r"((bf)[1]))

#define CPASYNC(dst, src) \
    asm volatile("cp.async.ca.shared.global [%0], [%1], 16;" :: "r"(dst), "l"(src) : "memory")
#define CPCOMMIT() asm volatile("cp.async.commit_group;" ::: "memory")
#define CPWAIT1()  asm volatile("cp.async.wait_group 1;" ::: "memory")
#define CPWAIT0()  asm volatile("cp.async.wait_group 0;" ::: "memory")

// ---------------------------------------------------------------------------
__global__ void init_kernel(const float* __restrict__ fused,
                            const float* __restrict__ b_ih,
                            const float* __restrict__ b_hh) {
    int i = blockIdx.x * blockDim.x + threadIdx.x;
    if (i < B * HID) {
        float v = fused[i];
        __nv_bfloat16 hi = __float2bfloat16(v);
        g_hhi[i] = hi;
        g_hlo[i] = __float2bfloat16(v - __bfloat162float(hi));
        g_c[i] = 0.0f;
    }
    if (i < 4 * HID) g_bsum[i] = b_ih[i] + b_hh[i];
    if (blockIdx.x == 0 && threadIdx.x < B) {
        g_amax[0][threadIdx.x] = 0ull;
        g_amax[1][threadIdx.x] = 0ull;
    }
}

// ---------------------------------------------------------------------------
__global__ void split_kernel(const float* __restrict__ src,
                             __nv_bfloat16* __restrict__ hi,
                             __nv_bfloat16* __restrict__ lo, size_t n) {
    size_t stride = (size_t)gridDim.x * blockDim.x * 4;
    for (size_t i = ((size_t)blockIdx.x * blockDim.x + threadIdx.x) * 4; i < n; i += stride) {
        float4 x = *(const float4*)(src + i);
        __nv_bfloat16 h0 = __float2bfloat16(x.x);
        __nv_bfloat16 h1 = __float2bfloat16(x.y);
        __nv_bfloat16 h2 = __float2bfloat16(x.z);
        __nv_bfloat16 h3 = __float2bfloat16(x.w);
        hi[i] = h0; hi[i + 1] = h1; hi[i + 2] = h2; hi[i + 3] = h3;
        lo[i]     = __float2bfloat16(x.x - __bfloat162float(h0));
        lo[i + 1] = __float2bfloat16(x.y - __bfloat162float(h1));
        lo[i + 2] = __float2bfloat16(x.z - __bfloat162float(h2));
        lo[i + 3] = __float2bfloat16(x.w - __bfloat162float(h3));
    }
}

// ---------------------------------------------------------------------------
// one-time: build unit-interleaved fused gate matrix G[3072][1536] (hi/lo).
// G[4u+g][k] = (k < HID ? W_ih : W_hh)[g*HID + u][k % HID]
// ---------------------------------------------------------------------------
__global__ void gsplit_kernel(const float* __restrict__ W_ih,
                              const float* __restrict__ W_hh) {
    size_t n = (size_t)4 * HID * GK;
    size_t stride = (size_t)gridDim.x * blockDim.x * 4;
    for (size_t i = ((size_t)blockIdx.x * blockDim.x + threadIdx.x) * 4; i < n; i += stride) {
        int r = (int)(i / GK), k = (int)(i % GK);
        int orow = (r & 3) * HID + (r >> 2);
        const float* src = (k < HID) ? (W_ih + (size_t)orow * HID + k)
                                     : (W_hh + (size_t)orow * HID + (k - HID));
        float4 x = *(const float4*)src;
        __nv_bfloat16 h0 = __float2bfloat16(x.x);
        __nv_bfloat16 h1 = __float2bfloat16(x.y);
        __nv_bfloat16 h2 = __float2bfloat16(x.z);
        __nv_bfloat16 h3 = __float2bfloat16(x.w);
        g_Ghi[i] = h0; g_Ghi[i + 1] = h1; g_Ghi[i + 2] = h2; g_Ghi[i + 3] = h3;
        g_Glo[i]     = __float2bfloat16(x.x - __bfloat162float(h0));
        g_Glo[i + 1] = __float2bfloat16(x.y - __bfloat162float(h1));
        g_Glo[i + 2] = __float2bfloat16(x.z - __bfloat162float(h2));
        g_Glo[i + 3] = __float2bfloat16(x.w - __bfloat162float(h3));
    }
}

// ---------------------------------------------------------------------------
__global__ void closed1_kernel(const float* __restrict__ fused,
                               const float* __restrict__ c1_W,
                               const float* __restrict__ c1_b) {
    __shared__ float w[HID];
    int j = blockIdx.x;
    for (int k = threadIdx.x; k < HID; k += 64) w[k] = c1_W[j * HID + k];
    __syncthreads();
    int b = threadIdx.x;
    float acc = 0.0f;
    for (int k = 0; k < HID; ++k) acc += fused[b * HID + k] * w[k];
    acc += c1_b[j];
    g_hidden[b * C1 + j] = fmaxf(acc, 0.0f);
}

__global__ void closed2_kernel(const float* __restrict__ c2_W,
                               const float* __restrict__ c2_b,
                               float* __restrict__ out) {
    int wid = threadIdx.x >> 5, lane = threadIdx.x & 31;
    int o = blockIdx.x * 4 + wid;
    int b = o >> 1, cls = o & 1;
    float acc = 0.0f;
    for (int k = lane; k < C1; k += 32)
        acc += g_hidden[b * C1 + k] * c2_W[cls * C1 + k];
#pragma unroll
    for (int off = 16; off; off >>= 1)
        acc += __shfl_xor_sync(0xFFFFFFFFu, acc, off);
    if (lane == 0) out[b * 2 + cls] = acc + c2_b[cls];
}

// ---------------------------------------------------------------------------
// fused gates + cell: block = 64 interleaved gate rows (16 units) x 64 batch,
// full K=1536 (chunks 0-11 = emb[tok], 12-23 = h). Epilogue does the LSTM
// cell update for this block's 16 units and writes h hi/lo planes.
// grid = 48 blocks.
// ---------------------------------------------------------------------------
__global__ void __launch_bounds__(256, 2)
gates_cell(int t, float* __restrict__ out) {
    __shared__ __align__(128) char sraw[32768];   // A hi 8K | A lo 8K | B hi 8K | B lo 8K
    __shared__ int tok_s[B];

    const int tid = threadIdx.x, wid = tid >> 5, lane = tid & 31;
    const int mw = wid >> 1, nw = wid & 1;
    const int mtile = blockIdx.x;                 // 0..47

    if (tid < B) {
        int tok = 0;
        if (t > 0) tok = (int)(~(unsigned int)(g_amax[(t - 1) & 1][tid]));
        tok_s[tid] = tok;
        if (mtile == 0) {
            g_amax[t & 1][tid] = 0ull;
            if (t > 0) out[2 * B + tid * TLEN + (t - 1)] = (float)tok;
        }
    }
    __syncthreads();

    const uint32_t sA_hi = smem_u32(sraw), sA_lo = sA_hi + 8192;
    const uint32_t sB_hi = sA_hi + 16384, sB_lo = sA_hi + 24576;

    // loader: 8 uint4 per thread per chunk
    const char* aSrc[4];
    const char* eSrc[4];
    const char* hSrc[4];
    uint32_t dsta[8];
#pragma unroll
    for (int i = 0; i < 8; ++i) {
        int s = tid + i * 256;
        int r = (s & 511) >> 3, g = s & 7;
        uint32_t dst = (uint32_t)(r * 128 + ((g ^ (r & 7)) * 16));
        if (i < 2) {            // A hi
            aSrc[i] = (const char*)(g_Ghi + (size_t)(mtile * 64 + r) * GK + g * 8);
            dsta[i] = sA_hi + dst;
        } else if (i < 4) {     // A lo
            aSrc[i] = (const char*)(g_Glo + (size_t)(mtile * 64 + r) * GK + g * 8);
            dsta[i] = sA_lo + dst;
        } else if (i < 6) {     // B hi: emb for k<768, h for k>=768
            eSrc[i - 4] = (const char*)(g_Ehi + (size_t)tok_s[r] * HID + g * 8);
            hSrc[i - 4] = (const char*)(g_hhi + r * HID + g * 8);
            dsta[i] = sB_hi + dst;
        } else {                // B lo
            eSrc[i - 4] = (const char*)(g_Elo + (size_t)tok_s[r] * HID + g * 8);
            hSrc[i - 4] = (const char*)(g_hlo + r * HID + g * 8);
            dsta[i] = sB_lo + dst;
        }
    }

    const int mA = mw * 16 + ((lane >> 3) & 1) * 8 + (lane & 7);
    const int gAo = lane >> 4;
    const int nB = nw * 32 + ((lane >> 4) & 1) * 8 + (lane & 7);
    const int gBo = (lane >> 3) & 1;

    float acc[4][4];
#pragma unroll
    for (int n = 0; n < 4; ++n)
#pragma unroll
        for (int j = 0; j < 4; ++j) acc[n][j] = 0.0f;

    uint4 pf[8];
#pragma unroll
    for (int i = 0; i < 4; ++i) pf[i] = *(const uint4*)(aSrc[i]);
#pragma unroll
    for (int i = 4; i < 8; ++i) pf[i] = *(const uint4*)(eSrc[i - 4]);

    for (int c = 0; c < GCH; ++c) {
#pragma unroll
        for (int i = 0; i < 8; ++i)
            asm volatile("st.shared.v4.b32 [%0], {%1, %2, %3, %4};"
                         :: "r"(dsta[i]), "r"(pf[i].x), "r"(pf[i].y),
                            "r"(pf[i].z), "r"(pf[i].w) : "memory");
        __syncthreads();

        if (c + 1 < GCH) {
            const int cn = c + 1;
#pragma unroll
            for (int i = 0; i < 4; ++i)
                pf[i] = *(const uint4*)(aSrc[i] + cn * 128);
            if (cn < NCHUNK) {
#pragma unroll
                for (int i = 4; i < 8; ++i)
                    pf[i] = *(const uint4*)(eSrc[i - 4] + cn * 128);
            } else {
#pragma unroll
                for (int i = 4; i < 8; ++i)
                    pf[i] = *(const uint4*)(hSrc[i - 4] + (cn - NCHUNK) * 128);
            }
        }

#pragma unroll
        for (int step = 0; step < 4; ++step) {
            const int g0 = step * 2;
            const int gA = g0 + gAo;
            const uint32_t offA = (uint32_t)(mA * 128 + ((gA ^ (mA & 7)) * 16));
            uint32_t ahi[4], alo[4];
            LDSM4(ahi[0], ahi[1], ahi[2], ahi[3], sA_hi + offA);
            LDSM4(alo[0], alo[1], alo[2], alo[3], sA_lo + offA);

            uint32_t bhi[4][2], blo[4][2];
#pragma unroll
            for (int ntp = 0; ntp < 2; ++ntp) {
                const int nr = nB + ntp * 16;
                const int gB = g0 + gBo;
                const uint32_t offB = (uint32_t)(nr * 128 + ((gB ^ (nr & 7)) * 16));
                LDSM4(bhi[ntp * 2][0], bhi[ntp * 2][1],
                      bhi[ntp * 2 + 1][0], bhi[ntp * 2 + 1][1], sB_hi + offB);
                LDSM4(blo[ntp * 2][0], blo[ntp * 2][1],
                      blo[ntp * 2 + 1][0], blo[ntp * 2 + 1][1], sB_lo + offB);
            }
#pragma unroll
            for (int n = 0; n < 4; ++n) {
                MMA16816(acc[n], ahi, bhi[n]);
                MMA16816(acc[n], ahi, blo[n]);
                MMA16816(acc[n], alo, bhi[n]);
            }
        }
        __syncthreads();
    }

    // ---- epilogue: dump acc to SMEM (reuses A-tile region), then cell ----
    float* gsm = (float*)sraw;   // 64 rows x 64 cols = 16 KB
    const int laneg = lane >> 2, lane4 = lane & 3;
    const int row_lo = mw * 16 + laneg;
#pragma unroll
    for (int n = 0; n < 4; ++n) {
        int col = nw * 32 + n * 8 + lane4 * 2;
        gsm[row_lo * 64 + col]       = acc[n][0];
        gsm[row_lo * 64 + col + 1]   = acc[n][1];
        gsm[(row_lo + 8) * 64 + col]     = acc[n][2];
        gsm[(row_lo + 8) * 64 + col + 1] = acc[n][3];
    }
    __syncthreads();

#pragma unroll
    for (int e = 0; e < 4; ++e) {
        int idx = tid * 4 + e;            // 0..1023
        int ul = idx >> 6, b = idx & 63;
        int u = mtile * 16 + ul;
        float gi = gsm[(4 * ul + 0) * 64 + b] + g_bsum[u];
        float gf = gsm[(4 * ul + 1) * 64 + b] + g_bsum[HID + u];
        float gg = gsm[(4 * ul + 2) * 64 + b] + g_bsum[2 * HID + u];
        float go = gsm[(4 * ul + 3) * 64 + b] + g_bsum[3 * HID + u];
        float cn = sigm(gf) * g_c[u * B + b] + sigm(gi) * tanhf(gg);
        g_c[u * B + b] = cn;
        float hn = sigm(go) * tanhf(cn);
        __nv_bfloat16 hi = __float2bfloat16(hn);
        g_hhi[b * HID + u] = hi;
        g_hlo[b * HID + u] = __float2bfloat16(hn - __bfloat162float(hi));
    }
}

// ---------------------------------------------------------------------------
// logits via HMMA split-bf16, MT=128 — EXACT round-7 version (2216us proven).
// ---------------------------------------------------------------------------
__global__ void __launch_bounds__(256, 2)
logits_mma(const float* __restrict__ out_b, int t) {
    extern __shared__ __align__(128) char dsm[];
    __shared__ unsigned long long skeys[4][B];

    const int tid = threadIdx.x, wid = tid >> 5, lane = tid & 31;
    const int mw = wid & 3, nw = wid >> 2;
    const int v0 = blockIdx.x * MT;
    const uint32_t sb0 = smem_u32(dsm);

    // loader: 3072 uint4 per stage, 12 per thread
    const char* srcp[12];
    uint32_t dstrel[12];
#pragma unroll
    for (int i = 0; i < 12; ++i) {
        int s = tid + i * 256;
        int g = s & 7, r;
        uint32_t roff;
        const __nv_bfloat16* base;
        if (s < 1024) {
            r = s >> 3; int v = v0 + r; if (v >= VSZ) v = VSZ - 1;
            base = g_Whi + (size_t)v * HID; roff = 0;
        } else if (s < 2048) {
            r = (s - 1024) >> 3; int v = v0 + r; if (v >= VSZ) v = VSZ - 1;
            base = g_Wlo + (size_t)v * HID; roff = 16384;
        } else if (s < 2560) {
            r = (s - 2048) >> 3; base = g_hhi + r * HID; roff = 32768;
        } else {
            r = (s - 2560) >> 3; base = g_hlo + r * HID; roff = 40960;
        }
        srcp[i] = (const char*)(base + g * 8);
        dstrel[i] = roff + (uint32_t)(r * 128 + ((g ^ (r & 7)) * 16));
    }

    const int mArb = mw * 32 + ((lane >> 3) & 1) * 8 + (lane & 7);
    const int gAo = lane >> 4;
    const int nB = nw * 32 + ((lane >> 4) & 1) * 8 + (lane & 7);
    const int gBo = (lane >> 3) & 1;

    float acc[2][4][4];
#pragma unroll
    for (int mi = 0; mi < 2; ++mi)
#pragma unroll
        for (int n = 0; n < 4; ++n)
#pragma unroll
            for (int j = 0; j < 4; ++j) acc[mi][n][j] = 0.0f;

    // stage 0
#pragma unroll
    for (int i = 0; i < 12; ++i) CPASYNC(sb0 + dstrel[i], srcp[i]);
    CPCOMMIT();
#pragma unroll
    for (int i = 0; i < 12; ++i) srcp[i] += KC * 2;

    for (int c = 0; c < NCHUNK; ++c) {
        const uint32_t sb = sb0 + (uint32_t)(c & 1) * LSTAGE;
        if (c + 1 < NCHUNK) {
            const uint32_t nbuf = sb0 + (uint32_t)((c + 1) & 1) * LSTAGE;
#pragma unroll
            for (int i = 0; i < 12; ++i) CPASYNC(nbuf + dstrel[i], srcp[i]);
            CPCOMMIT();
#pragma unroll
            for (int i = 0; i < 12; ++i) srcp[i] += KC * 2;
            CPWAIT1();
        } else {
            CPWAIT0();
        }
        __syncthreads();

        const uint32_t sWhiB = sb, sWloB = sb + 16384;
        const uint32_t sHhiB = sb + 32768, sHloB = sb + 40960;
#pragma unroll
        for (int step = 0; step < 4; ++step) {
            const int g0 = step * 2;
            const int gA = g0 + gAo, gB = g0 + gBo;
            uint32_t ahi[2][4], alo[2][4];
#pragma unroll
            for (int mi = 0; mi < 2; ++mi) {
                const int row = mArb + mi * 16;
                const uint32_t offA = (uint32_t)(row * 128 + ((gA ^ (row & 7)) * 16));
                LDSM4(ahi[mi][0], ahi[mi][1], ahi[mi][2], ahi[mi][3], sWhiB + offA);
                LDSM4(alo[mi][0], alo[mi][1], alo[mi][2], alo[mi][3], sWloB + offA);
            }
            uint32_t bhi[4][2], blo[4][2];
#pragma unroll
            for (int ntp = 0; ntp < 2; ++ntp) {
                const int nr = nB + ntp * 16;
                const uint32_t offB = (uint32_t)(nr * 128 + ((gB ^ (nr & 7)) * 16));
                LDSM4(bhi[ntp * 2][0], bhi[ntp * 2][1],
                      bhi[ntp * 2 + 1][0], bhi[ntp * 2 + 1][1], sHhiB + offB);
                LDSM4(blo[ntp * 2][0], blo[ntp * 2][1],
                      blo[ntp * 2 + 1][0], blo[ntp * 2 + 1][1], sHloB + offB);
            }
#pragma unroll
            for (int mi = 0; mi < 2; ++mi)
#pragma unroll
                for (int n = 0; n < 4; ++n) {
                    MMA16816(acc[mi][n], ahi[mi], bhi[n]);
                    MMA16816(acc[mi][n], ahi[mi], blo[n]);
                    MMA16816(acc[mi][n], alo[mi], bhi[n]);
                }
        }
        __syncthreads();
    }

    // epilogue: bias + deterministic argmax
    const int laneg = lane >> 2, lane4 = lane & 3;
    float biasL[2], biasH[2];
    bool vL[2], vH[2];
    unsigned int niL[2], niH[2];
#pragma unroll
    for (int mi = 0; mi < 2; ++mi) {
        int ml = v0 + mw * 32 + mi * 16 + laneg, mh = ml + 8;
        vL[mi] = ml < VSZ; vH[mi] = mh < VSZ;
        biasL[mi] = vL[mi] ? out_b[ml] : 0.0f;
        biasH[mi] = vH[mi] ? out_b[mh] : 0.0f;
        niL[mi] = ~(unsigned int)ml; niH[mi] = ~(unsigned int)mh;
    }
#pragma unroll
    for (int n = 0; n < 4; ++n) {
        unsigned long long kA = 0ull, kB = 0ull;
#pragma unroll
        for (int mi = 0; mi < 2; ++mi) {
            if (vL[mi]) {
                unsigned long long k0 = ((unsigned long long)ford(acc[mi][n][0] + biasL[mi]) << 32) | niL[mi];
                unsigned long long k1 = ((unsigned long long)ford(acc[mi][n][1] + biasL[mi]) << 32) | niL[mi];
                if (k0 > kA) kA = k0;
                if (k1 > kB) kB = k1;
            }
            if (vH[mi]) {
                unsigned long long k2 = ((unsigned long long)ford(acc[mi][n][2] + biasH[mi]) << 32) | niH[mi];
                unsigned long long k3 = ((unsigned long long)ford(acc[mi][n][3] + biasH[mi]) << 32) | niH[mi];
                if (k2 > kA) kA = k2;
                if (k3 > kB) kB = k3;
            }
        }
#pragma unroll
        for (int off = 4; off < 32; off <<= 1) {
            unsigned long long oA = __shfl_xor_sync(0xFFFFFFFFu, kA, off);
            unsigned long long oB = __shfl_xor_sync(0xFFFFFFFFu, kB, off);
            if (oA > kA) kA = oA;
            if (oB > kB) kB = oB;
        }
        if (laneg == 0) {
            int ncol = nw * 32 + n * 8 + lane4 * 2;
            skeys[mw][ncol]     = kA;
            skeys[mw][ncol + 1] = kB;
        }
    }
    __syncthreads();
    if (tid < B) {
        unsigned long long k = skeys[0][tid];
        if (skeys[1][tid] > k) k = skeys[1][tid];
        if (skeys[2][tid] > k) k = skeys[2][tid];
        if (skeys[3][tid] > k) k = skeys[3][tid];
        atomicMax(&g_amax[t & 1][tid], k);
    }
}

// ---------------------------------------------------------------------------
__global__ void final_kernel(float* __restrict__ out) {
    int b = threadIdx.x;
    if (b < B) {
        int tok = (int)(~(unsigned int)(g_amax[(TLEN - 1) & 1][b]));
        out[2 * B + b * TLEN + (TLEN - 1)] = (float)tok;
    }
}

// ---------------------------------------------------------------------------
extern "C" void kernel_launch(void* const* d_in, const int* in_sizes, int n_in,
                              void* d_out, int out_size) {
    const float* fused = (const float*)d_in[0];
    const float* emb   = (const float*)d_in[1];
    const float* W_ih  = (const float*)d_in[2];
    const float* W_hh  = (const float*)d_in[3];
    const float* b_ih  = (const float*)d_in[4];
    const float* b_hh  = (const float*)d_in[5];
    const float* out_W = (const float*)d_in[6];
    const float* out_b = (const float*)d_in[7];
    const float* c1_W  = (const float*)d_in[8];
    const float* c1_b  = (const float*)d_in[9];
    const float* c2_W  = (const float*)d_in[10];
    const float* c2_b  = (const float*)d_in[11];
    float* out = (float*)d_out;

    cudaFuncSetAttribute(logits_mma, cudaFuncAttributeMaxDynamicSharedMemorySize,
                         2 * LSTAGE);

    __nv_bfloat16 *pWhi, *pWlo, *pEhi, *pElo;
    cudaGetSymbolAddress((void**)&pWhi, g_Whi);
    cudaGetSymbolAddress((void**)&pWlo, g_Wlo);
    cudaGetSymbolAddress((void**)&pEhi, g_Ehi);
    cudaGetSymbolAddress((void**)&pElo, g_Elo);

    init_kernel<<<(B * HID + 255) / 256, 256>>>(fused, b_ih, b_hh);
    split_kernel<<<2048, 256>>>(out_W, pWhi, pWlo, (size_t)VSZ * HID);
    split_kernel<<<2048, 256>>>(emb, pEhi, pElo, (size_t)VSZ * HID);
    gsplit_kernel<<<1024, 256>>>(W_ih, W_hh);
    closed1_kernel<<<C1, 64>>>(fused, c1_W, c1_b);
    closed2_kernel<<<32, 128>>>(c2_W, c2_b, out);

    for (int t = 0; t < TLEN; ++t) {
        gates_cell<<<48, 256>>>(t, out);
        logits_mma<<<GRID_L, 256, 2 * LSTAGE>>>(out_b, t);
    }
    final_kernel<<<1, 64>>>(out);
}

// round 10
// speedup vs baseline: 1.5664x; 1.2259x over previous
#include <cuda_runtime.h>
#include <cuda_bf16.h>
#include <cstdint>

#define B    64
#define HID  768
#define VSZ  30000
#define TLEN 32
#define C1   512

// logits HMMA tiling (round-6 proven: MT=64, static smem, reg prefetch)
#define MT      64
#define KC      64
#define NCHUNK  (HID / KC)              // 12
#define GRID_L  ((VSZ + MT - 1) / MT)   // 469

// gates HMMA tiling (round-7 proven)
#define KSG     4                       // split-K
#define CHG     6                       // chunks of 64 per split (384 k)

__device__ float g_c[B * HID];          // transposed: [u][b]
__device__ float g_hidden[B * C1];
__device__ unsigned long long g_amax[2][B];
__device__ float g_gpartT[KSG][4 * HID][B];
__device__ __nv_bfloat16 g_Whi[(size_t)VSZ * HID];
__device__ __nv_bfloat16 g_Wlo[(size_t)VSZ * HID];
__device__ __nv_bfloat16 g_Ehi[(size_t)VSZ * HID];
__device__ __nv_bfloat16 g_Elo[(size_t)VSZ * HID];
__device__ __nv_bfloat16 g_WihHi[4 * HID * HID];
__device__ __nv_bfloat16 g_WihLo[4 * HID * HID];
__device__ __nv_bfloat16 g_WhhHi[4 * HID * HID];
__device__ __nv_bfloat16 g_WhhLo[4 * HID * HID];
__device__ __nv_bfloat16 g_hhi[B * HID];
__device__ __nv_bfloat16 g_hlo[B * HID];

__device__ __forceinline__ unsigned int ford(float f) {
    unsigned int u = __float_as_uint(f);
    return u ^ (((int)u >> 31) | 0x80000000u);
}
__device__ __forceinline__ float sigm(float x) { return 1.0f / (1.0f + expf(-x)); }

__device__ __forceinline__ uint32_t smem_u32(const void* p) {
    uint32_t a;
    asm("{ .reg .u64 t; cvta.to.shared.u64 t, %1; cvt.u32.u64 %0, t; }" : "=r"(a) : "l"(p));
    return a;
}

#define LDSM4(r0, r1, r2, r3, addr) \
    asm volatile("ldmatrix.sync.aligned.m8n8.x4.shared.b16 {%0,%1,%2,%3}, [%4];" \
                 : "=r"(r0), "=r"(r1), "=r"(r2), "=r"(r3) : "r"(addr))

#define MMA16816(d, a, bf) \
    asm volatile("mma.sync.aligned.m16n8k16.row.col.f32.bf16.bf16.f32 " \
                 "{%0,%1,%2,%3}, {%4,%5,%6,%7}, {%8,%9}, {%0,%1,%2,%3};" \
                 : "+f"((d)[0]), "+f"((d)[1]), "+f"((d)[2]), "+f"((d)[3]) \
                 : "r"((a)[0]), "r"((a)[1]), "r"((a)[2]), "r"((a)[3]), \
                   "r"((bf)[0]), "r"((bf)[1]))

// ---------------------------------------------------------------------------
__global__ void init_kernel(const float* __restrict__ fused) {
    int i = blockIdx.x * blockDim.x + threadIdx.x;
    if (i < B * HID) {
        float v = fused[i];
        __nv_bfloat16 hi = __float2bfloat16(v);
        g_hhi[i] = hi;
        g_hlo[i] = __float2bfloat16(v - __bfloat162float(hi));
        g_c[i] = 0.0f;
    }
    if (blockIdx.x == 0 && threadIdx.x < B) {
        g_amax[0][threadIdx.x] = 0ull;
        g_amax[1][threadIdx.x] = 0ull;
    }
}

// ---------------------------------------------------------------------------
__global__ void split_kernel(const float* __restrict__ src,
                             __nv_bfloat16* __restrict__ hi,
                             __nv_bfloat16* __restrict__ lo, size_t n) {
    size_t stride = (size_t)gridDim.x * blockDim.x * 4;
    for (size_t i = ((size_t)blockIdx.x * blockDim.x + threadIdx.x) * 4; i < n; i += stride) {
        float4 x = *(const float4*)(src + i);
        __nv_bfloat16 h0 = __float2bfloat16(x.x);
        __nv_bfloat16 h1 = __float2bfloat16(x.y);
        __nv_bfloat16 h2 = __float2bfloat16(x.z);
        __nv_bfloat16 h3 = __float2bfloat16(x.w);
        hi[i] = h0; hi[i + 1] = h1; hi[i + 2] = h2; hi[i + 3] = h3;
        lo[i]     = __float2bfloat16(x.x - __bfloat162float(h0));
        lo[i + 1] = __float2bfloat16(x.y - __bfloat162float(h1));
        lo[i + 2] = __float2bfloat16(x.z - __bfloat162float(h2));
        lo[i + 3] = __float2bfloat16(x.w - __bfloat162float(h3));
    }
}

// ---------------------------------------------------------------------------
__global__ void closed1_kernel(const float* __restrict__ fused,
                               const float* __restrict__ c1_W,
                               const float* __restrict__ c1_b) {
    __shared__ float w[HID];
    int j = blockIdx.x;
    for (int k = threadIdx.x; k < HID; k += 64) w[k] = c1_W[j * HID + k];
    __syncthreads();
    int b = threadIdx.x;
    float acc = 0.0f;
    for (int k = 0; k < HID; ++k) acc += fused[b * HID + k] * w[k];
    acc += c1_b[j];
    g_hidden[b * C1 + j] = fmaxf(acc, 0.0f);
}

__global__ void closed2_kernel(const float* __restrict__ c2_W,
                               const float* __restrict__ c2_b,
                               float* __restrict__ out) {
    int wid = threadIdx.x >> 5, lane = threadIdx.x & 31;
    int o = blockIdx.x * 4 + wid;
    int b = o >> 1, cls = o & 1;
    float acc = 0.0f;
    for (int k = lane; k < C1; k += 32)
        acc += g_hidden[b * C1 + k] * c2_W[cls * C1 + k];
#pragma unroll
    for (int off = 16; off; off >>= 1)
        acc += __shfl_xor_sync(0xFFFFFFFFu, acc, off);
    if (lane == 0) out[b * 2 + cls] = acc + c2_b[cls];
}

// ---------------------------------------------------------------------------
// gates via HMMA split-bf16 (exact round-7 structure)
// ---------------------------------------------------------------------------
__global__ void __launch_bounds__(256, 2)
gates_mma(int t, float* __restrict__ out) {
    __shared__ __align__(128) __nv_bfloat16 sAhi[64 * KC];
    __shared__ __align__(128) __nv_bfloat16 sAlo[64 * KC];
    __shared__ __align__(128) __nv_bfloat16 sBhi[B * KC];
    __shared__ __align__(128) __nv_bfloat16 sBlo[B * KC];
    __shared__ int tok_s[B];

    const int tid = threadIdx.x, wid = tid >> 5, lane = tid & 31;
    const int mw = wid >> 1, nw = wid & 1;
    const int mtile = blockIdx.x;
    const int ks = blockIdx.y;
    const bool is_x = ks < 2;
    const int kbase = (ks & 1) * 384;

    if (tid < B) {
        int tok = 0;
        if (t > 0) tok = (int)(~(unsigned int)(g_amax[(t - 1) & 1][tid]));
        tok_s[tid] = tok;
        if (mtile == 0 && ks == 0) {
            g_amax[t & 1][tid] = 0ull;
            if (t > 0) out[2 * B + tid * TLEN + (t - 1)] = (float)tok;
        }
    }
    __syncthreads();

    const __nv_bfloat16* srcp[8];
    uint32_t dsta[8];
#pragma unroll
    for (int i = 0; i < 8; ++i) {
        int s = tid + i * 256;
        int r = (s & 511) >> 3, g = s & 7;
        uint32_t dst = (uint32_t)(r * 128 + ((g ^ (r & 7)) * 16));
        if (s < 512) {
            int m = mtile * 64 + r;
            srcp[i] = (is_x ? g_WihHi : g_WhhHi) + (size_t)m * HID + kbase + g * 8;
            dsta[i] = smem_u32(sAhi) + dst;
        } else if (s < 1024) {
            int m = mtile * 64 + r;
            srcp[i] = (is_x ? g_WihLo : g_WhhLo) + (size_t)m * HID + kbase + g * 8;
            dsta[i] = smem_u32(sAlo) + dst;
        } else if (s < 1536) {
            srcp[i] = is_x ? (g_Ehi + (size_t)tok_s[r] * HID + kbase + g * 8)
                           : (g_hhi + r * HID + kbase + g * 8);
            dsta[i] = smem_u32(sBhi) + dst;
        } else {
            srcp[i] = is_x ? (g_Elo + (size_t)tok_s[r] * HID + kbase + g * 8)
                           : (g_hlo + r * HID + kbase + g * 8);
            dsta[i] = smem_u32(sBlo) + dst;
        }
    }

    const int mA = mw * 16 + ((lane >> 3) & 1) * 8 + (lane & 7);
    const int gAo = lane >> 4;
    const int nB = nw * 32 + ((lane >> 4) & 1) * 8 + (lane & 7);
    const int gBo = (lane >> 3) & 1;
    const uint32_t sAhiB = smem_u32(sAhi), sAloB = smem_u32(sAlo);
    const uint32_t sBhiB = smem_u32(sBhi), sBloB = smem_u32(sBlo);

    float acc[4][4];
#pragma unroll
    for (int n = 0; n < 4; ++n)
#pragma unroll
        for (int j = 0; j < 4; ++j) acc[n][j] = 0.0f;

    uint4 pf[8];
#pragma unroll
    for (int i = 0; i < 8; ++i) { pf[i] = *(const uint4*)srcp[i]; srcp[i] += KC; }

    for (int c = 0; c < CHG; ++c) {
#pragma unroll
        for (int i = 0; i < 8; ++i)
            asm volatile("st.shared.v4.b32 [%0], {%1, %2, %3, %4};"
                         :: "r"(dsta[i]), "r"(pf[i].x), "r"(pf[i].y),
                            "r"(pf[i].z), "r"(pf[i].w) : "memory");
        __syncthreads();

        if (c + 1 < CHG) {
#pragma unroll
            for (int i = 0; i < 8; ++i) { pf[i] = *(const uint4*)srcp[i]; srcp[i] += KC; }
        }

#pragma unroll
        for (int step = 0; step < 4; ++step) {
            const int g0 = step * 2;
            const int gA = g0 + gAo;
            const uint32_t offA = (uint32_t)(mA * 128 + ((gA ^ (mA & 7)) * 16));
            uint32_t ahi[4], alo[4];
            LDSM4(ahi[0], ahi[1], ahi[2], ahi[3], sAhiB + offA);
            LDSM4(alo[0], alo[1], alo[2], alo[3], sAloB + offA);

            uint32_t bhi[4][2], blo[4][2];
#pragma unroll
            for (int ntp = 0; ntp < 2; ++ntp) {
                const int nr = nB + ntp * 16;
                const int gB = g0 + gBo;
                const uint32_t offB = (uint32_t)(nr * 128 + ((gB ^ (nr & 7)) * 16));
                LDSM4(bhi[ntp * 2][0], bhi[ntp * 2][1],
                      bhi[ntp * 2 + 1][0], bhi[ntp * 2 + 1][1], sBhiB + offB);
                LDSM4(blo[ntp * 2][0], blo[ntp * 2][1],
                      blo[ntp * 2 + 1][0], blo[ntp * 2 + 1][1], sBloB + offB);
            }
#pragma unroll
            for (int n = 0; n < 4; ++n) {
                MMA16816(acc[n], ahi, bhi[n]);
                MMA16816(acc[n], ahi, blo[n]);
                MMA16816(acc[n], alo, bhi[n]);
            }
        }
        __syncthreads();
    }

    const int laneg = lane >> 2, lane4 = lane & 3;
    const int row_lo = mtile * 64 + mw * 16 + laneg;
    const int row_hi = row_lo + 8;
#pragma unroll
    for (int n = 0; n < 4; ++n) {
        int col = nw * 32 + n * 8 + lane4 * 2;
        *(float2*)&g_gpartT[ks][row_lo][col] = make_float2(acc[n][0], acc[n][1]);
        *(float2*)&g_gpartT[ks][row_hi][col] = make_float2(acc[n][2], acc[n][3]);
    }
}

// ---------------------------------------------------------------------------
// cell: reduce KSG partials (fixed order), biases, LSTM nonlinearities,
// emit bf16 hi/lo split of h. (exact round-7)
// ---------------------------------------------------------------------------
__global__ void cell_kernel(const float* __restrict__ b_ih,
                            const float* __restrict__ b_hh, int t) {
    int idx = blockIdx.x * blockDim.x + threadIdx.x;
    if (idx >= B * HID) return;
    int b = idx & (B - 1), u = idx >> 6;

    float gi = b_ih[u] + b_hh[u];
    float gf = b_ih[HID + u] + b_hh[HID + u];
    float gg = b_ih[2 * HID + u] + b_hh[2 * HID + u];
    float go = b_ih[3 * HID + u] + b_hh[3 * HID + u];
#pragma unroll
    for (int s = 0; s < KSG; ++s) {
        gi += g_gpartT[s][u][b];
        gf += g_gpartT[s][HID + u][b];
        gg += g_gpartT[s][2 * HID + u][b];
        go += g_gpartT[s][3 * HID + u][b];
    }
    float cn = sigm(gf) * g_c[u * B + b] + sigm(gi) * tanhf(gg);
    g_c[u * B + b] = cn;
    float hn = sigm(go) * tanhf(cn);
    __nv_bfloat16 hi = __float2bfloat16(hn);
    g_hhi[b * HID + u] = hi;
    g_hlo[b * HID + u] = __float2bfloat16(hn - __bfloat162float(hi));
}

// ---------------------------------------------------------------------------
// logits via HMMA split-bf16 — EXACT round-6 version (MT=64, static smem,
// register prefetch, grid 469). Proven ~37us/step inside the 2471 run.
// ---------------------------------------------------------------------------
__global__ void __launch_bounds__(256, 2)
logits_mma(const float* __restrict__ out_b, int t) {
    __shared__ __align__(128) __nv_bfloat16 sWhi[MT * KC];
    __shared__ __align__(128) __nv_bfloat16 sWlo[MT * KC];
    __shared__ __align__(128) __nv_bfloat16 sHhi[B * KC];
    __shared__ __align__(128) __nv_bfloat16 sHlo[B * KC];
    __shared__ unsigned long long skeys[4][B];

    const int tid = threadIdx.x, wid = tid >> 5, lane = tid & 31;
    const int mw = wid >> 1, nw = wid & 1;
    const int v0 = blockIdx.x * MT;

    const __nv_bfloat16* srcp[8];
    uint32_t dsta[8];
#pragma unroll
    for (int i = 0; i < 8; ++i) {
        int s = tid + i * 256;
        int r = (s & 511) >> 3, g = s & 7;
        uint32_t dst = (uint32_t)(r * 128 + ((g ^ (r & 7)) * 16));
        if (s < 512) {
            int v = v0 + r; if (v >= VSZ) v = VSZ - 1;
            srcp[i] = g_Whi + (size_t)v * HID + g * 8;
            dsta[i] = smem_u32(sWhi) + dst;
        } else if (s < 1024) {
            int v = v0 + r; if (v >= VSZ) v = VSZ - 1;
            srcp[i] = g_Wlo + (size_t)v * HID + g * 8;
            dsta[i] = smem_u32(sWlo) + dst;
        } else if (s < 1536) {
            srcp[i] = g_hhi + r * HID + g * 8;
            dsta[i] = smem_u32(sHhi) + dst;
        } else {
            srcp[i] = g_hlo + r * HID + g * 8;
            dsta[i] = smem_u32(sHlo) + dst;
        }
    }

    const int mA = mw * 16 + ((lane >> 3) & 1) * 8 + (lane & 7);
    const int gAo = lane >> 4;
    const int nB = nw * 32 + ((lane >> 4) & 1) * 8 + (lane & 7);
    const int gBo = (lane >> 3) & 1;
    const uint32_t sWhiB = smem_u32(sWhi), sWloB = smem_u32(sWlo);
    const uint32_t sHhiB = smem_u32(sHhi), sHloB = smem_u32(sHlo);

    float acc[4][4];
#pragma unroll
    for (int n = 0; n < 4; ++n)
#pragma unroll
        for (int j = 0; j < 4; ++j) acc[n][j] = 0.0f;

    uint4 pf[8];
#pragma unroll
    for (int i = 0; i < 8; ++i) { pf[i] = *(const uint4*)srcp[i]; srcp[i] += KC; }

    for (int c = 0; c < NCHUNK; ++c) {
#pragma unroll
        for (int i = 0; i < 8; ++i)
            asm volatile("st.shared.v4.b32 [%0], {%1, %2, %3, %4};"
                         :: "r"(dsta[i]), "r"(pf[i].x), "r"(pf[i].y),
                            "r"(pf[i].z), "r"(pf[i].w) : "memory");
        __syncthreads();

        if (c + 1 < NCHUNK) {
#pragma unroll
            for (int i = 0; i < 8; ++i) { pf[i] = *(const uint4*)srcp[i]; srcp[i] += KC; }
        }

#pragma unroll
        for (int step = 0; step < 4; ++step) {
            const int g0 = step * 2;
            const int gA = g0 + gAo;
            const uint32_t offA = (uint32_t)(mA * 128 + ((gA ^ (mA & 7)) * 16));
            uint32_t ahi[4], alo[4];
            LDSM4(ahi[0], ahi[1], ahi[2], ahi[3], sWhiB + offA);
            LDSM4(alo[0], alo[1], alo[2], alo[3], sWloB + offA);

            uint32_t bhi[4][2], blo[4][2];
#pragma unroll
            for (int ntp = 0; ntp < 2; ++ntp) {
                const int nr = nB + ntp * 16;
                const int gB = g0 + gBo;
                const uint32_t offB = (uint32_t)(nr * 128 + ((gB ^ (nr & 7)) * 16));
                LDSM4(bhi[ntp * 2][0], bhi[ntp * 2][1],
                      bhi[ntp * 2 + 1][0], bhi[ntp * 2 + 1][1], sHhiB + offB);
                LDSM4(blo[ntp * 2][0], blo[ntp * 2][1],
                      blo[ntp * 2 + 1][0], blo[ntp * 2 + 1][1], sHloB + offB);
            }
#pragma unroll
            for (int n = 0; n < 4; ++n) {
                MMA16816(acc[n], ahi, bhi[n]);
                MMA16816(acc[n], ahi, blo[n]);
                MMA16816(acc[n], alo, bhi[n]);
            }
        }
        __syncthreads();
    }

    const int laneg = lane >> 2, lane4 = lane & 3;
    const int m_lo = v0 + mw * 16 + laneg;
    const int m_hi = m_lo + 8;
    const bool val_lo = m_lo < VSZ, val_hi = m_hi < VSZ;
    const float bias_lo = val_lo ? out_b[m_lo] : 0.0f;
    const float bias_hi = val_hi ? out_b[m_hi] : 0.0f;
    const unsigned int ni_lo = ~(unsigned int)m_lo, ni_hi = ~(unsigned int)m_hi;

#pragma unroll
    for (int n = 0; n < 4; ++n) {
        unsigned long long kA = 0ull, kB = 0ull;
        if (val_lo) {
            kA = ((unsigned long long)ford(acc[n][0] + bias_lo) << 32) | ni_lo;
            kB = ((unsigned long long)ford(acc[n][1] + bias_lo) << 32) | ni_lo;
        }
        if (val_hi) {
            unsigned long long k2 = ((unsigned long long)ford(acc[n][2] + bias_hi) << 32) | ni_hi;
            unsigned long long k3 = ((unsigned long long)ford(acc[n][3] + bias_hi) << 32) | ni_hi;
            if (k2 > kA) kA = k2;
            if (k3 > kB) kB = k3;
        }
#pragma unroll
        for (int off = 4; off < 32; off <<= 1) {
            unsigned long long oA = __shfl_xor_sync(0xFFFFFFFFu, kA, off);
            unsigned long long oB = __shfl_xor_sync(0xFFFFFFFFu, kB, off);
            if (oA > kA) kA = oA;
            if (oB > kB) kB = oB;
        }
        if (laneg == 0) {
            int ncol = nw * 32 + n * 8 + lane4 * 2;
            skeys[mw][ncol]     = kA;
            skeys[mw][ncol + 1] = kB;
        }
    }
    __syncthreads();
    if (tid < B) {
        unsigned long long k = skeys[0][tid];
        if (skeys[1][tid] > k) k = skeys[1][tid];
        if (skeys[2][tid] > k) k = skeys[2][tid];
        if (skeys[3][tid] > k) k = skeys[3][tid];
        atomicMax(&g_amax[t & 1][tid], k);
    }
}

// ---------------------------------------------------------------------------
__global__ void final_kernel(float* __restrict__ out) {
    int b = threadIdx.x;
    if (b < B) {
        int tok = (int)(~(unsigned int)(g_amax[(TLEN - 1) & 1][b]));
        out[2 * B + b * TLEN + (TLEN - 1)] = (float)tok;
    }
}

// ---------------------------------------------------------------------------
extern "C" void kernel_launch(void* const* d_in, const int* in_sizes, int n_in,
                              void* d_out, int out_size) {
    const float* fused = (const float*)d_in[0];
    const float* emb   = (const float*)d_in[1];
    const float* W_ih  = (const float*)d_in[2];
    const float* W_hh  = (const float*)d_in[3];
    const float* b_ih  = (const float*)d_in[4];
    const float* b_hh  = (const float*)d_in[5];
    const float* out_W = (const float*)d_in[6];
    const float* out_b = (const float*)d_in[7];
    const float* c1_W  = (const float*)d_in[8];
    const float* c1_b  = (const float*)d_in[9];
    const float* c2_W  = (const float*)d_in[10];
    const float* c2_b  = (const float*)d_in[11];
    float* out = (float*)d_out;

    __nv_bfloat16 *pWhi, *pWlo, *pEhi, *pElo, *pIhHi, *pIhLo, *pHhHi, *pHhLo;
    cudaGetSymbolAddress((void**)&pWhi, g_Whi);
    cudaGetSymbolAddress((void**)&pWlo, g_Wlo);
    cudaGetSymbolAddress((void**)&pEhi, g_Ehi);
    cudaGetSymbolAddress((void**)&pElo, g_Elo);
    cudaGetSymbolAddress((void**)&pIhHi, g_WihHi);
    cudaGetSymbolAddress((void**)&pIhLo, g_WihLo);
    cudaGetSymbolAddress((void**)&pHhHi, g_WhhHi);
    cudaGetSymbolAddress((void**)&pHhLo, g_WhhLo);

    init_kernel<<<(B * HID + 255) / 256, 256>>>(fused);
    split_kernel<<<2048, 256>>>(out_W, pWhi, pWlo, (size_t)VSZ * HID);
    split_kernel<<<2048, 256>>>(emb, pEhi, pElo, (size_t)VSZ * HID);
    split_kernel<<<512, 256>>>(W_ih, pIhHi, pIhLo, (size_t)4 * HID * HID);
    split_kernel<<<512, 256>>>(W_hh, pHhHi, pHhLo, (size_t)4 * HID * HID);
    closed1_kernel<<<C1, 64>>>(fused, c1_W, c1_b);
    closed2_kernel<<<32, 128>>>(c2_W, c2_b, out);

    dim3 ggrid(4 * HID / 64, KSG);   // (48, 4)
    for (int t = 0; t < TLEN; ++t) {
        gates_mma<<<ggrid, 256>>>(t, out);
        cell_kernel<<<(B * HID + 255) / 256, 256>>>(b_ih, b_hh, t);
        logits_mma<<<GRID_L, 256>>>(out_b, t);
    }
    final_kernel<<<1, 64>>>(out);
}